// round 1
// baseline (speedup 1.0000x reference)
#include <cuda_runtime.h>
#include <stdint.h>

// Problem constants (from reference setup_inputs)
#define BB 8
#define LL 512
#define CC 6
#define NTOT (BB * LL)     // 4096
#define KK 9
#define BIGF 1e10f

// Output layout (float32, concatenated reference outputs):
//  dknn  [N,K]            @ 0
//  src   [N,K]            @ 1*N*K
//  dst   [N,K]            @ 2*N*K
//  valid [N,K]            @ 3*N*K
//  glb   [2, B*(2L-1)]    @ 4*N*K
//  seq   [2, B*2(L-2)]    @ 4*N*K + 2*B*(2L-1)

__global__ __launch_bounds__(LL)
void knn_rows_kernel(const float* __restrict__ X,
                     const int*   __restrict__ AP,
                     const int*   __restrict__ S,
                     const int*   __restrict__ SEC,
                     float*       __restrict__ out)
{
    const int i    = blockIdx.x;        // global row index (node)
    const int b    = i / LL;
    const int base = b * LL;
    const int j    = threadIdx.x;       // local column (node within graph)
    const int gj   = base + j;

    __shared__ float xi[CC][3];
    __shared__ float sqi[CC];
    __shared__ int   padi[CC];
    __shared__ int   si_s;
    __shared__ unsigned long long key[LL];
    __shared__ unsigned long long warpmin[LL / 32];
    __shared__ unsigned long long winner;
    __shared__ float res_d[KK];
    __shared__ int   res_j[KK];

    // Stage row-i data into shared memory
    if (j < CC * 3) ((float*)xi)[j] = X[i * CC * 3 + j];
    if (j < CC)     padi[j] = (AP[i * CC + j] == 0);
    if (j == 0)     si_s = S[i];
    __syncthreads();
    if (j < CC) {
        sqi[j] = xi[j][0]*xi[j][0] + xi[j][1]*xi[j][1] + xi[j][2]*xi[j][2];
    }
    __syncthreads();

    // Load column-j node into registers
    float xj[CC][3];
    float sqj[CC];
    bool  padj[CC];
    #pragma unroll
    for (int c = 0; c < CC; c++) {
        xj[c][0] = X[gj * CC * 3 + c * 3 + 0];
        xj[c][1] = X[gj * CC * 3 + c * 3 + 1];
        xj[c][2] = X[gj * CC * 3 + c * 3 + 2];
        sqj[c]   = xj[c][0]*xj[c][0] + xj[c][1]*xj[c][1] + xj[c][2]*xj[c][2];
        padj[c]  = (AP[gj * CC + c] == 0);
    }
    const int sj = S[gj];

    float dist;
    if (si_s == 0 || sj == 0) {
        dist = BIGF;    // global-node mask applied exactly as in reference (where -> exact 1e10)
    } else {
        const float INF = __int_as_float(0x7f800000);
        float mn_un  = INF;   // min d2 over unpadded channel pairs
        float mn_all = INF;   // min d2 over all channel pairs
        #pragma unroll
        for (int c = 0; c < CC; c++) {
            const float a0 = xi[c][0], a1 = xi[c][1], a2 = xi[c][2];
            const float sa = sqi[c];
            const bool  pa = padi[c];
            #pragma unroll
            for (int d = 0; d < CC; d++) {
                float dot = a0 * xj[d][0] + a1 * xj[d][1] + a2 * xj[d][2];
                float d2  = sa + sqj[d] - 2.0f * dot;
                d2 = fmaxf(d2, 0.0f);
                mn_all = fminf(mn_all, d2);
                if (!(pa || padj[d])) mn_un = fminf(mn_un, d2);
            }
        }
        // sqrt is monotone + correctly rounded: min(sqrt(x)) == sqrt(min(x)) bitwise.
        // If any unpadded pair exists its sqrt < 1e10 <= any padded value, so it wins.
        if (mn_un < INF) dist = sqrtf(mn_un);
        else             dist = sqrtf(mn_all) + BIGF;  // all pairs padded
    }

    // Pack (dist, j): non-negative float bits are order-preserving in u32,
    // so u64-min == (smallest dist, lowest index) — matches jax.lax.top_k ties.
    key[j] = ((unsigned long long)__float_as_uint(dist) << 32) | (unsigned int)j;
    __syncthreads();

    const int lane = j & 31;
    const int wid  = j >> 5;

    for (int m = 0; m < KK; m++) {
        unsigned long long v = key[j];
        #pragma unroll
        for (int o = 16; o > 0; o >>= 1) {
            unsigned long long u = __shfl_down_sync(0xffffffffu, v, o);
            v = (u < v) ? u : v;
        }
        if (lane == 0) warpmin[wid] = v;
        __syncthreads();
        if (j < 16) {
            unsigned long long v2 = warpmin[j];
            #pragma unroll
            for (int o = 8; o > 0; o >>= 1) {
                unsigned long long u2 = __shfl_down_sync(0x0000ffffu, v2, o);
                v2 = (u2 < v2) ? u2 : v2;
            }
            if (j == 0) winner = v2;
        }
        __syncthreads();
        const unsigned long long w = winner;
        const int wj = (int)(w & 0xffffffffull);
        if (j == wj) key[j] = 0xffffffffffffffffull;   // remove winner
        if (j == 0) {
            res_d[m] = __uint_as_float((unsigned int)(w >> 32));
            res_j[m] = wj;
        }
        __syncthreads();
    }

    // Emit the four per-edge arrays
    if (j < KK) {
        const float d  = res_d[j];
        const int   lj = res_j[j];
        const int   dg = base + lj;
        const bool  valid = (d < BIGF) && (SEC[i] == SEC[dg]);
        const int   NK = NTOT * KK;
        out[0 * NK + i * KK + j] = d;
        out[1 * NK + i * KK + j] = (float)i;
        out[2 * NK + i * KK + j] = valid ? (float)dg : -1.0f;
        out[3 * NK + i * KK + j] = valid ? 1.0f : 0.0f;
    }
}

// Constant (data-independent) global + sequential edge lists.
__global__ void edges_kernel(float* __restrict__ out)
{
    const int t  = blockIdx.x * blockDim.x + threadIdx.x;
    const int GL = 2 * LL - 1;        // 1023 per graph
    const int NG = BB * GL;           // 8184
    const int SL = 2 * (LL - 2);      // 1020 per graph
    const int NS = BB * SL;           // 8160
    float* glb = out + 4 * NTOT * KK;
    float* seq = glb + 2 * NG;

    if (t < NG) {
        const int b = t / GL, e = t % GL, off = b * LL;
        int s, d;
        if (e < LL) { s = 0;           d = e; }
        else        { s = e - LL + 1;  d = 0; }
        glb[t]      = (float)(s + off);
        glb[NG + t] = (float)(d + off);
    }
    if (t < NS) {
        const int b = t / SL, e = t % SL, off = b * LL;
        const int h = LL - 2;          // 510
        int s, d;
        if (e < h) { s = 1 + e;       d = 2 + e; }
        else       { s = e - h + 2;   d = e - h + 1; }
        seq[t]      = (float)(s + off);
        seq[NS + t] = (float)(d + off);
    }
}

extern "C" void kernel_launch(void* const* d_in, const int* in_sizes, int n_in,
                              void* d_out, int out_size)
{
    const float* X   = (const float*)d_in[0];   // [N, C, 3]
    const int*   AP  = (const int*)  d_in[1];   // [N, C]
    const int*   S   = (const int*)  d_in[2];   // [N]
    const int*   SEC = (const int*)  d_in[3];   // [N]
    // d_in[4] = batch_id (derivable), d_in[5] = k (constant 9)
    float* out = (float*)d_out;

    knn_rows_kernel<<<NTOT, LL>>>(X, AP, S, SEC, out);

    const int NG = BB * (2 * LL - 1);           // 8184 (>= NS)
    edges_kernel<<<(NG + 255) / 256, 256>>>(out);
}

// round 2
// speedup vs baseline: 3.1804x; 3.1804x over previous
#include <cuda_runtime.h>
#include <stdint.h>

// Problem constants
#define BB 8
#define LL 512
#define CC 6
#define NTOT (BB * LL)     // 4096
#define KK 9
#define BIGF 1e10f
#define PENF 1e19f

#define ROWS_PB 16
#define NBLK (NTOT / ROWS_PB)   // 256
#define NTHR 512                // 16 warps, warp <-> row

// Output layout (float32):
//  dknn [N,K] @0 | src [N,K] @NK | dst [N,K] @2NK | valid [N,K] @3NK
//  glb [2, B*(2L-1)] @4NK | seq [2, B*2(L-2)] after

__global__ __launch_bounds__(NTHR, 1)
void knn_fused_kernel(const float* __restrict__ X,
                      const int*   __restrict__ AP,
                      const int*   __restrict__ S,
                      const int*   __restrict__ SEC,
                      float*       __restrict__ out)
{
    // Column data: [m][ch][lane] float4 {2x, 2y, 2z, |x|^2 + pad*1e19}
    __shared__ float4 s_col[ROWS_PB * CC * 32];   // 3072 * 16B = 48KB

    const int tid  = threadIdx.x;
    const int bid  = blockIdx.x;
    const int lane = tid & 31;
    const int w    = tid >> 5;               // warp id == row-in-block
    const int gbase = (bid >> 5) << 9;       // graph base node (32 blocks/graph)
    const int i     = bid * ROWS_PB + w;     // this warp's global row

    // ---- constant edge arrays (first 64 blocks), independent of smem ----
    {
        const int GL = 2 * LL - 1;           // 1023
        const int NG = BB * GL;              // 8184
        const int SL = 2 * (LL - 2);         // 1020
        const int NS = BB * SL;              // 8160
        const int g  = bid * NTHR + tid;
        float* glb = out + 4 * NTOT * KK;
        if (g < 2 * NG) {
            const int r = g / NG, t = g - r * NG;
            const int b = t / GL, e = t - b * GL, off = b * LL;
            int s, d;
            if (e < LL) { s = 0;          d = e; }
            else        { s = e - LL + 1; d = 0; }
            glb[g] = (float)((r == 0 ? s : d) + off);
        } else if (g < 2 * NG + 2 * NS) {
            const int g2 = g - 2 * NG;
            const int r = g2 / NS, t = g2 - r * NS;
            const int b = t / SL, e = t - b * SL, off = b * LL;
            const int h = LL - 2;
            int s, d;
            if (e < h) { s = 1 + e;     d = 2 + e; }
            else       { s = e - h + 2; d = e - h + 1; }
            glb[2 * NG + g2] = (float)((r == 0 ? s : d) + off);
        }
    }

    // ---- fill column smem: 3072 entries, 6 per thread ----
    #pragma unroll
    for (int rep = 0; rep < 6; rep++) {
        const int e    = tid + rep * NTHR;       // [0, 3072)
        const int elane = e & 31;
        const int mc    = e >> 5;                // m*6 + ch
        const int ch    = mc % CC;
        const int m     = mc / CC;
        const int j     = (m << 5) | elane;
        const int node  = gbase + j;
        const float x = X[node * 18 + ch * 3 + 0];
        const float y = X[node * 18 + ch * 3 + 1];
        const float z = X[node * 18 + ch * 3 + 2];
        const float sq = x * x + y * y + z * z;          // same expr as reference-matching R1
        const float pen = (AP[node * CC + ch] == 0) ? PENF : 0.0f;
        s_col[e] = make_float4(2.0f * x, 2.0f * y, 2.0f * z, sq + pen);
    }

    // ---- row data (warp-uniform) ----
    float a0[CC], a1[CC], a2[CC], sap[CC];
    #pragma unroll
    for (int c = 0; c < CC; c++) {
        a0[c] = X[i * 18 + c * 3 + 0];
        a1[c] = X[i * 18 + c * 3 + 1];
        a2[c] = X[i * 18 + c * 3 + 2];
        const float sq = a0[c] * a0[c] + a1[c] * a1[c] + a2[c] * a2[c];
        sap[c] = sq + ((AP[i * CC + c] == 0) ? PENF : 0.0f);
    }
    const bool rowBOS = (S[i] == 0);
    const int  seci   = SEC[i];
    const float INF   = __int_as_float(0x7f800000);

    __syncthreads();

    // ---- distance + key build: 16 columns per lane ----
    unsigned long long K[16];
    #pragma unroll
    for (int m = 0; m < ROWS_PB; m++) {
        const int j = (m << 5) | lane;
        float mn0 = INF, mn1 = INF, mn2 = INF, mn3 = INF, mn4 = INF, mn5 = INF;
        #pragma unroll
        for (int d = 0; d < CC; d++) {
            const float4 q = s_col[(m * CC + d) * 32 + lane];
            // dot2 == 2*dot bitwise (x2 is exact); d2 == (sa+sqj) - 2*dot single-rounded
            {
                const float dot = a0[0] * q.x + a1[0] * q.y + a2[0] * q.z;
                mn0 = fminf(mn0, (sap[0] + q.w) - dot);
            }
            {
                const float dot = a0[1] * q.x + a1[1] * q.y + a2[1] * q.z;
                mn1 = fminf(mn1, (sap[1] + q.w) - dot);
            }
            {
                const float dot = a0[2] * q.x + a1[2] * q.y + a2[2] * q.z;
                mn2 = fminf(mn2, (sap[2] + q.w) - dot);
            }
            {
                const float dot = a0[3] * q.x + a1[3] * q.y + a2[3] * q.z;
                mn3 = fminf(mn3, (sap[3] + q.w) - dot);
            }
            {
                const float dot = a0[4] * q.x + a1[4] * q.y + a2[4] * q.z;
                mn4 = fminf(mn4, (sap[4] + q.w) - dot);
            }
            {
                const float dot = a0[5] * q.x + a1[5] * q.y + a2[5] * q.z;
                mn5 = fminf(mn5, (sap[5] + q.w) - dot);
            }
        }
        float mn = fminf(fminf(fminf(mn0, mn1), fminf(mn2, mn3)), fminf(mn4, mn5));
        float dist;
        if (mn >= 1e18f) dist = BIGF;                 // all channel pairs padded (rare; value-insensitive)
        else             dist = sqrtf(fmaxf(mn, 0.0f));
        const bool colBOS = (S[gbase + j] == 0);
        if (rowBOS || colBOS) dist = BIGF;            // exact 1e10, matches reference where()
        K[m] = ((unsigned long long)__float_as_uint(dist) << 32) | (unsigned int)j;
    }

    // ---- lane-local bitonic sort of 16 keys (ascending) ----
    #pragma unroll
    for (int k = 2; k <= 16; k <<= 1) {
        #pragma unroll
        for (int jj = k >> 1; jj > 0; jj >>= 1) {
            #pragma unroll
            for (int t2 = 0; t2 < 16; t2++) {
                const int p = t2 ^ jj;
                if (p > t2) {
                    const bool up = ((t2 & k) == 0) || (k == 16);
                    unsigned long long x = K[t2], y = K[p];
                    const bool sw = (y < x);
                    unsigned long long lo = sw ? y : x;
                    unsigned long long hi = sw ? x : y;
                    if (up) { K[t2] = lo; K[p] = hi; }
                    else    { K[t2] = hi; K[p] = lo; }
                }
            }
        }
    }

    // ---- 9-round warp merge (butterfly min over lane heads) + output ----
    const int NK = NTOT * KK;
    #pragma unroll
    for (int m = 0; m < KK; m++) {
        unsigned long long v = K[0];
        #pragma unroll
        for (int o = 16; o > 0; o >>= 1) {
            const unsigned long long u = __shfl_xor_sync(0xffffffffu, v, o);
            v = (u < v) ? u : v;
        }
        if (K[0] == v) {      // unique winner (index embedded in key)
            #pragma unroll
            for (int s2 = 0; s2 < KK; s2++) K[s2] = K[s2 + 1];
        }
        if (lane == m) {
            const float d  = __uint_as_float((unsigned int)(v >> 32));
            const int   jl = (int)(v & 0xffffffffull);
            const int   dg = gbase + jl;
            const bool  val = (d < BIGF) && (seci == SEC[dg]);
            out[0 * NK + i * KK + m] = d;
            out[1 * NK + i * KK + m] = (float)i;
            out[2 * NK + i * KK + m] = val ? (float)dg : -1.0f;
            out[3 * NK + i * KK + m] = val ? 1.0f : 0.0f;
        }
    }
}

extern "C" void kernel_launch(void* const* d_in, const int* in_sizes, int n_in,
                              void* d_out, int out_size)
{
    const float* X   = (const float*)d_in[0];   // [N, C, 3]
    const int*   AP  = (const int*)  d_in[1];   // [N, C]
    const int*   S   = (const int*)  d_in[2];   // [N]
    const int*   SEC = (const int*)  d_in[3];   // [N]
    float* out = (float*)d_out;

    knn_fused_kernel<<<NBLK, NTHR>>>(X, AP, S, SEC, out);
}

// round 4
// speedup vs baseline: 3.3159x; 1.0426x over previous
#include <cuda_runtime.h>
#include <stdint.h>

// Problem constants
#define BB 8
#define LL 512
#define CC 6
#define NTOT (BB * LL)     // 4096
#define KK 9
#define BIGF 1e10f
#define PENF 1e19f

#define ROWS_PB 16
#define NBLK (NTOT / ROWS_PB)   // 256
#define NTHR 1024               // 32 warps: warp w -> (row w>>1, column-half w&1)
#define CPL 8                   // candidates per lane (256 cols / 32 lanes)

// Output layout (float32):
//  dknn [N,K] @0 | src [N,K] @NK | dst [N,K] @2NK | valid [N,K] @3NK
//  glb [2, B*(2L-1)] @4NK | seq [2, B*2(L-2)] after

__global__ __launch_bounds__(NTHR, 1)
void knn_fused_kernel(const float* __restrict__ X,
                      const int*   __restrict__ AP,
                      const int*   __restrict__ S,
                      const int*   __restrict__ SEC,
                      float*       __restrict__ out)
{
    // Column data: [j>>5][ch][j&31] float4 {2x, 2y, 2z, |x|^2 + (pad|BOS)*1e19}
    __shared__ float4 s_col[(LL / 32) * CC * 32];          // 3072 * 16B = 48KB
    __shared__ unsigned long long s_res[ROWS_PB][2][KK];   // per-half sorted top-9

    const int tid  = threadIdx.x;
    const int bid  = blockIdx.x;
    const int lane = tid & 31;
    const int w    = tid >> 5;
    const int r    = w >> 1;                 // row within block
    const int h    = w & 1;                  // column half
    const int gbase = (bid >> 5) << 9;       // graph base node
    const int i     = bid * ROWS_PB + r;     // global row

    // ---- constant edge arrays (data-independent) ----
    {
        const int GL = 2 * LL - 1;           // 1023
        const int NG = BB * GL;              // 8184
        const int SL = 2 * (LL - 2);         // 1020
        const int NS = BB * SL;              // 8160
        const int g  = bid * NTHR + tid;
        float* glb = out + 4 * NTOT * KK;
        if (g < 2 * NG) {
            const int rr = g / NG, t = g - rr * NG;
            const int b = t / GL, e = t - b * GL, off = b * LL;
            int s, d;
            if (e < LL) { s = 0;          d = e; }
            else        { s = e - LL + 1; d = 0; }
            glb[g] = (float)((rr == 0 ? s : d) + off);
        } else if (g < 2 * NG + 2 * NS) {
            const int g2 = g - 2 * NG;
            const int rr = g2 / NS, t = g2 - rr * NS;
            const int b = t / SL, e = t - b * SL, off = b * LL;
            const int hh = LL - 2;
            int s, d;
            if (e < hh) { s = 1 + e;      d = 2 + e; }
            else        { s = e - hh + 2; d = e - hh + 1; }
            glb[2 * NG + g2] = (float)((rr == 0 ? s : d) + off);
        }
    }

    // ---- fill column smem: 3072 entries, 3 per thread ----
    #pragma unroll
    for (int rep = 0; rep < 3; rep++) {
        const int e     = tid + rep * NTHR;      // [0, 3072)
        const int elane = e & 31;
        const int mc    = e >> 5;                // m*6 + ch
        const int ch    = mc % CC;
        const int m     = mc / CC;
        const int j     = (m << 5) | elane;
        const int node  = gbase + j;
        const float x = X[node * 18 + ch * 3 + 0];
        const float y = X[node * 18 + ch * 3 + 1];
        const float z = X[node * 18 + ch * 3 + 2];
        const float sq = x * x + y * y + z * z;
        const float pen = (AP[node * CC + ch] == 0 || S[node] == 0) ? PENF : 0.0f;
        s_col[e] = make_float4(2.0f * x, 2.0f * y, 2.0f * z, sq + pen);
    }

    // ---- row data (warp-uniform); BOS folded into penalty ----
    float a0[CC], a1[CC], a2[CC], sap[CC];
    const float rpen = (S[i] == 0) ? PENF : 0.0f;
    #pragma unroll
    for (int c = 0; c < CC; c++) {
        a0[c] = X[i * 18 + c * 3 + 0];
        a1[c] = X[i * 18 + c * 3 + 1];
        a2[c] = X[i * 18 + c * 3 + 2];
        const float sq = a0[c] * a0[c] + a1[c] * a1[c] + a2[c] * a2[c];
        sap[c] = sq + ((AP[i * CC + c] == 0) ? PENF : rpen);
    }
    const float INF = __int_as_float(0x7f800000);

    __syncthreads();

    // ---- distance + key build: 8 columns per lane (this warp's half) ----
    unsigned long long K[CPL];
    #pragma unroll
    for (int m = 0; m < CPL; m++) {
        const int mf = h * CPL + m;              // full column group
        const int j  = (mf << 5) | lane;         // local column index
        float mn0 = INF, mn1 = INF, mn2 = INF, mn3 = INF, mn4 = INF, mn5 = INF;
        #pragma unroll
        for (int d = 0; d < CC; d++) {
            const float4 q = s_col[(mf * CC + d) * 32 + lane];
            { const float dot = a0[0]*q.x + a1[0]*q.y + a2[0]*q.z; mn0 = fminf(mn0, (sap[0]+q.w) - dot); }
            { const float dot = a0[1]*q.x + a1[1]*q.y + a2[1]*q.z; mn1 = fminf(mn1, (sap[1]+q.w) - dot); }
            { const float dot = a0[2]*q.x + a1[2]*q.y + a2[2]*q.z; mn2 = fminf(mn2, (sap[2]+q.w) - dot); }
            { const float dot = a0[3]*q.x + a1[3]*q.y + a2[3]*q.z; mn3 = fminf(mn3, (sap[3]+q.w) - dot); }
            { const float dot = a0[4]*q.x + a1[4]*q.y + a2[4]*q.z; mn4 = fminf(mn4, (sap[4]+q.w) - dot); }
            { const float dot = a0[5]*q.x + a1[5]*q.y + a2[5]*q.z; mn5 = fminf(mn5, (sap[5]+q.w) - dot); }
        }
        const float mn = fminf(fminf(fminf(mn0, mn1), fminf(mn2, mn3)), fminf(mn4, mn5));
        const float dist = (mn >= 1e18f) ? BIGF : sqrtf(fmaxf(mn, 0.0f));
        K[m] = ((unsigned long long)__float_as_uint(dist) << 32) | (unsigned int)j;
    }

    // ---- lane-local bitonic sort of 8 keys (ascending) ----
    #pragma unroll
    for (int k = 2; k <= 8; k <<= 1) {
        #pragma unroll
        for (int jj = k >> 1; jj > 0; jj >>= 1) {
            #pragma unroll
            for (int t2 = 0; t2 < CPL; t2++) {
                const int p = t2 ^ jj;
                if (p > t2) {
                    const bool up = ((t2 & k) == 0) || (k == 8);
                    unsigned long long x = K[t2], y = K[p];
                    const bool sw = (y < x);
                    unsigned long long lo = sw ? y : x;
                    unsigned long long hi = sw ? x : y;
                    if (up) { K[t2] = lo; K[p] = hi; }
                    else    { K[t2] = hi; K[p] = lo; }
                }
            }
        }
    }

    // ---- 9-round warp merge over lane heads -> this half's sorted top-9 ----
    #pragma unroll
    for (int m = 0; m < KK; m++) {
        unsigned long long v = K[0];
        #pragma unroll
        for (int o = 16; o > 0; o >>= 1) {
            const unsigned long long u = __shfl_xor_sync(0xffffffffu, v, o);
            v = (u < v) ? u : v;
        }
        if (K[0] == v) {    // unique winner: shift out, pad with MAX
            #pragma unroll
            for (int s2 = 0; s2 < CPL - 1; s2++) K[s2] = K[s2 + 1];
            K[CPL - 1] = 0xffffffffffffffffull;
        }
        if (lane == m) s_res[r][h][m] = v;
    }

    __syncthreads();

    // ---- cross-half merge by rank (u64 keys are unique) + output ----
    if (w < ROWS_PB && lane < 2 * KK) {
        const int row  = w;
        const int side = (lane < KK) ? 0 : 1;
        const int m    = (lane < KK) ? lane : lane - KK;
        const unsigned long long x = s_res[row][side][m];
        int cnt = 0;
        #pragma unroll
        for (int q = 0; q < KK; q++)
            cnt += (s_res[row][side ^ 1][q] < x) ? 1 : 0;
        const int rank = m + cnt;
        if (rank < KK) {
            const int gi  = bid * ROWS_PB + row;
            const float d = __uint_as_float((unsigned int)(x >> 32));
            const int  jl = (int)(x & 0xffffffffull);
            const int  dg = gbase + jl;
            const bool val = (d < BIGF) && (SEC[gi] == SEC[dg]);
            const int  NK = NTOT * KK;
            out[0 * NK + gi * KK + rank] = d;
            out[1 * NK + gi * KK + rank] = (float)gi;
            out[2 * NK + gi * KK + rank] = val ? (float)dg : -1.0f;
            out[3 * NK + gi * KK + rank] = val ? 1.0f : 0.0f;
        }
    }
}

extern "C" void kernel_launch(void* const* d_in, const int* in_sizes, int n_in,
                              void* d_out, int out_size)
{
    const float* X   = (const float*)d_in[0];   // [N, C, 3]
    const int*   AP  = (const int*)  d_in[1];   // [N, C]
    const int*   S   = (const int*)  d_in[2];   // [N]
    const int*   SEC = (const int*)  d_in[3];   // [N]
    float* out = (float*)d_out;

    knn_fused_kernel<<<NBLK, NTHR>>>(X, AP, S, SEC, out);
}